// round 4
// baseline (speedup 1.0000x reference)
#include <cuda_runtime.h>
#include <cstdint>

#define N_ATOMS 50000
#define M_NBR   32
#define NE      (N_ATOMS * M_NBR)   // 1,600,000 edges
#define NBR_F   64
#define ATOM_F  128
#define SH_DIM  9
#define INV_SQRT_F 0.08838834764831845f  // 1/sqrt(128)

// Per-atom accumulators (scratch; device globals per allocation rules)
__device__ float g_S[N_ATOMS];
__device__ float g_C[N_ATOMS];

// ---------------------------------------------------------------------------
// Kernel 0: zero the accumulators
// ---------------------------------------------------------------------------
__global__ void zero_kernel() {
    int i = blockIdx.x * blockDim.x + threadIdx.x;
    if (i < N_ATOMS) { g_S[i] = 0.0f; g_C[i] = 0.0f; }
}

// ---------------------------------------------------------------------------
// Kernel 1: per-edge scalar = softplus(radial @ w1 + b1) . w2[:,0] + b2[0]
//           atomically accumulate into g_S[idx], g_C[idx]
// One thread per edge. w1 (64x64) staged in shared (broadcast LDS reads).
// ---------------------------------------------------------------------------
__global__ __launch_bounds__(128) void edge_kernel(
    const float* __restrict__ nbr_fea,
    const int*   __restrict__ nbr_idx,   // int32! (JAX x64 disabled)
    const float* __restrict__ w1,
    const float* __restrict__ b1,
    const float* __restrict__ w2,
    const float* __restrict__ b2)
{
    __shared__ float s_w1[NBR_F * NBR_F];   // 16 KB, row k contiguous in j
    __shared__ float s_w2[NBR_F];           // column 0 of w2
    __shared__ float s_b1[NBR_F];

    int tid = threadIdx.x;
    for (int i = tid; i < NBR_F * NBR_F; i += blockDim.x) s_w1[i] = w1[i];
    if (tid < NBR_F) {
        s_w2[tid] = w2[tid * SH_DIM];   // w2[:,0]
        s_b1[tid] = b1[tid];
    }
    __syncthreads();

    int e = blockIdx.x * blockDim.x + tid;
    if (e >= NE) return;

    const float4* r4 = (const float4*)(nbr_fea + (size_t)e * NBR_F);

    float h[NBR_F];
    #pragma unroll
    for (int j = 0; j < NBR_F; j++) h[j] = s_b1[j];

    // h = radial @ w1  (outer loop rolled to keep I-footprint small)
    for (int kq = 0; kq < NBR_F / 4; kq++) {
        float4 rv = r4[kq];
        float rr[4] = {rv.x, rv.y, rv.z, rv.w};
        #pragma unroll
        for (int s = 0; s < 4; s++) {
            const float* wrow = &s_w1[(kq * 4 + s) * NBR_F];
            #pragma unroll
            for (int j = 0; j < NBR_F; j++)
                h[j] = fmaf(rr[s], wrow[j], h[j]);
        }
    }

    // r0 = softplus(h) . w2[:,0] + b2[0]
    float r0 = b2[0];
    #pragma unroll
    for (int j = 0; j < NBR_F; j++) {
        float x = h[j];
        // jax.nn.softplus(x) = max(x,0) + log1p(exp(-|x|))
        float sp = fmaxf(x, 0.0f) + __logf(1.0f + __expf(-fabsf(x)));
        r0 = fmaf(sp, s_w2[j], r0);
    }

    int a = nbr_idx[e];
    // Defensive clamp: no index interpretation can trap
    a = (a < 0) ? 0 : (a >= N_ATOMS ? N_ATOMS - 1 : a);
    atomicAdd(&g_S[a], r0);
    atomicAdd(&g_C[a], 1.0f);
}

// ---------------------------------------------------------------------------
// Kernel 2: out[i,:] = (atom_fea[i,:] @ tp_w) * g_S[i] * INV_SQRT_F / max(g_C[i],1)
// Tiled GEMM: 32 atoms x 128 cols per block, 256 threads, k-tiles of 32.
// ---------------------------------------------------------------------------
__global__ __launch_bounds__(256) void out_kernel(
    const float* __restrict__ atom_fea,
    const float* __restrict__ tp_w,
    float* __restrict__ out)
{
    __shared__ float s_tw[32 * ATOM_F];   // 16 KB  (k-tile x 128 cols)
    __shared__ float s_af[32 * 32];       // 4 KB   (32 atoms x k-tile)

    int tid  = threadIdx.x;
    int base = blockIdx.x * 32;
    int j    = tid & 127;      // output column
    int ag   = tid >> 7;       // atom-group 0/1 (16 atoms each)

    float acc[16];
    #pragma unroll
    for (int a = 0; a < 16; a++) acc[a] = 0.0f;

    for (int kt = 0; kt < ATOM_F / 32; kt++) {
        __syncthreads();
        for (int i = tid; i < 32 * ATOM_F; i += 256)
            s_tw[i] = tp_w[(size_t)(kt * 32) * ATOM_F + i];
        for (int i = tid; i < 32 * 32; i += 256) {
            int a = i >> 5, kk = i & 31;
            int atom = base + a;
            s_af[i] = (atom < N_ATOMS)
                        ? atom_fea[(size_t)atom * ATOM_F + kt * 32 + kk]
                        : 0.0f;
        }
        __syncthreads();

        #pragma unroll
        for (int kk = 0; kk < 32; kk++) {
            float tw = s_tw[kk * ATOM_F + j];          // conflict-free, stride 1
            #pragma unroll
            for (int a = 0; a < 16; a++)               // broadcast LDS
                acc[a] = fmaf(s_af[(ag * 16 + a) * 32 + kk], tw, acc[a]);
        }
    }

    #pragma unroll
    for (int a = 0; a < 16; a++) {
        int atom = base + ag * 16 + a;
        if (atom < N_ATOMS) {
            float c = g_C[atom];
            float scale = g_S[atom] * INV_SQRT_F / fmaxf(c, 1.0f);
            out[(size_t)atom * ATOM_F + j] = acc[a] * scale;
        }
    }
}

// ---------------------------------------------------------------------------
// Launch
// ---------------------------------------------------------------------------
extern "C" void kernel_launch(void* const* d_in, const int* in_sizes, int n_in,
                              void* d_out, int out_size)
{
    const float* atom_fea = (const float*)d_in[0];
    const float* nbr_fea  = (const float*)d_in[1];
    const int*   nbr_idx  = (const int*)d_in[2];
    const float* w1       = (const float*)d_in[3];
    const float* b1       = (const float*)d_in[4];
    const float* w2       = (const float*)d_in[5];
    const float* b2       = (const float*)d_in[6];
    const float* tp_w     = (const float*)d_in[7];
    float*       out      = (float*)d_out;

    zero_kernel<<<(N_ATOMS + 255) / 256, 256>>>();
    edge_kernel<<<NE / 128, 128>>>(nbr_fea, nbr_idx, w1, b1, w2, b2);
    out_kernel<<<(N_ATOMS + 31) / 32, 256>>>(atom_fea, tp_w, out);
}